// round 14
// baseline (speedup 1.0000x reference)
#include <cuda_runtime.h>
#include <cuda_bf16.h>
#include <math.h>
#include <cstdint>

#define BATCH  4096
#define NIN    32
#define NHID   128
#define NOUT   30000
#define NCLUST 10000
#define BN_EPS 1e-3f

#define NCC      20000
#define NCC_PAD  20480
#define NBLK     313
#define CTAX     37            // 1184 CTAs = exactly 4 waves @ occ 2

// ---- scratch ----
__device__ float g_h[BATCH * NHID];
__device__ float g_sum[NHID];
__device__ float g_sumsq[NHID];
__device__ float g_scale[NHID];
__device__ float g_shift[NHID];
__device__ __nv_bfloat16 g_Ah[BATCH * NHID];
__device__ __nv_bfloat16 g_Al[BATCH * NHID];
__device__ __nv_bfloat16 g_Bh[NCC_PAD * NHID];
__device__ __nv_bfloat16 g_Bl[NCC_PAD * NHID];
__device__ float2 g_b2p[10240];

// ---- MUFU-free exp / rcp ----------------------------------------------------
__device__ __forceinline__ float fexp(float x) {
    float t  = x * 1.4426950408889634f;
    float rf = t + 12582912.0f;
    int   ri = __float_as_int(rf) - 0x4B400000;
    float f  = t - (rf - 12582912.0f);
    float p = 1.3333558e-3f;
    p = fmaf(p, f, 9.6181291e-3f);
    p = fmaf(p, f, 5.5504109e-2f);
    p = fmaf(p, f, 2.4022651e-1f);
    p = fmaf(p, f, 6.9314718e-1f);
    p = fmaf(p, f, 1.0f);
    return __int_as_float(__float_as_int(p) + (ri << 23));
}
__device__ __forceinline__ float frcp(float d) {
    float r = __int_as_float(0x7EF127EAu - __float_as_int(d));
    #pragma unroll
    for (int i = 0; i < 2; i++) {
        float e = fmaf(-d, r, 1.0f);
        r = fmaf(r, e, r);
    }
    return r;
}

__device__ __forceinline__ uint32_t smem_u32(const void* p) {
    uint32_t a;
    asm("{ .reg .u64 t; cvta.to.shared.u64 t, %1; cvt.u32.u64 %0, t; }"
        : "=r"(a) : "l"(p));
    return a;
}
__device__ __forceinline__ void cp16(uint32_t dst, const void* src) {
    asm volatile("cp.async.cg.shared.global [%0], [%1], 16;"
                 :: "r"(dst), "l"(src));
}
__device__ __forceinline__ void cp_commit() {
    asm volatile("cp.async.commit_group;");
}
__device__ __forceinline__ void cp_wait0() {
    asm volatile("cp.async.wait_group 0;");
}
__device__ __forceinline__ void ldsm_x4(uint32_t& r0, uint32_t& r1,
                                        uint32_t& r2, uint32_t& r3, uint32_t a) {
    asm volatile("ldmatrix.sync.aligned.m8n8.x4.shared.b16 {%0,%1,%2,%3}, [%4];"
                 : "=r"(r0), "=r"(r1), "=r"(r2), "=r"(r3) : "r"(a));
}
__device__ __forceinline__ void mma16816(float* c, const uint32_t* a,
                                         const uint32_t* b) {
    asm volatile("mma.sync.aligned.m16n8k16.row.col.f32.bf16.bf16.f32 "
                 "{%0,%1,%2,%3}, {%4,%5,%6,%7}, {%8,%9}, {%0,%1,%2,%3};"
                 : "+f"(c[0]), "+f"(c[1]), "+f"(c[2]), "+f"(c[3])
                 : "r"(a[0]), "r"(a[1]), "r"(a[2]), "r"(a[3]),
                   "r"(b[0]), "r"(b[1]));
}

// ---------------------------------------------------------------------------
__global__ void k_init() {
    int i = threadIdx.x;
    if (i < NHID) { g_sum[i] = 0.0f; g_sumsq[i] = 0.0f; }
}

__global__ void k_h(const float* __restrict__ z,
                    const float* __restrict__ W1,
                    const float* __restrict__ b1) {
    __shared__ float zs[128][33];
    __shared__ float ws[128][33];
    __shared__ float ps[2][128];
    __shared__ float psq[2][128];

    const int tid   = threadIdx.x;
    const int rbase = blockIdx.x * 128;

    for (int idx = tid; idx < 128 * NIN; idx += 256) {
        int r = idx >> 5, k = idx & 31;
        zs[r][k] = z[(rbase + r) * NIN + k];
        ws[r][k] = W1[idx];
    }
    __syncthreads();

    const int col = tid & 127;
    const int rh  = tid >> 7;
    const float bb = b1[col];
    float ls = 0.0f, lsq = 0.0f;

    for (int r = rh * 64; r < rh * 64 + 64; r++) {
        float acc = bb;
        #pragma unroll
        for (int k = 0; k < NIN; k++)
            acc = fmaf(zs[r][k], ws[col][k], acc);
        g_h[(rbase + r) * NHID + col] = acc;
        ls += acc;
        lsq = fmaf(acc, acc, lsq);
    }
    ps[rh][col]  = ls;
    psq[rh][col] = lsq;
    __syncthreads();
    if (tid < 128) {
        atomicAdd(&g_sum[tid],   ps[0][tid]  + ps[1][tid]);
        atomicAdd(&g_sumsq[tid], psq[0][tid] + psq[1][tid]);
    }
}

__global__ void k_bn(const float* __restrict__ gamma,
                     const float* __restrict__ beta) {
    int c = threadIdx.x;
    if (c >= NHID) return;
    const float inv_b = 1.0f / (float)BATCH;
    float mu   = g_sum[c] * inv_b;
    float var  = g_sumsq[c] * inv_b - mu * mu;
    float rstd = rsqrtf(var + BN_EPS);
    float sc   = gamma[c] * rstd;
    g_scale[c] = sc;
    g_shift[c] = beta[c] - mu * sc;
}

__global__ void k_split_h() {
    const int idx = blockIdx.x * 256 + threadIdx.x;
    if (idx >= BATCH * NHID) return;
    const int k = idx & 127;
    float v = fmaxf(fmaf(g_h[idx], g_scale[k], g_shift[k]), 0.0f);
    __nv_bfloat16 hi = __float2bfloat16_rn(v);
    g_Ah[idx] = hi;
    g_Al[idx] = __float2bfloat16_rn(v - __bfloat162float(hi));
}

__global__ void k_split_w(const float* __restrict__ W2,
                          const float* __restrict__ b2) {
    const int idx = blockIdx.x * 256 + threadIdx.x;
    if (idx < 10240) {
        float2 bp = make_float2(0.0f, 0.0f);
        if (idx < NCLUST)
            bp = make_float2(b2[3 * idx + 1], b2[3 * idx + 2]);
        g_b2p[idx] = bp;
    }
    if (idx >= NCC_PAD * NHID) return;
    const int cc = idx >> 7;
    const int k  = idx & 127;
    float w = 0.0f;
    if (cc < NCC) {
        const int c = cc >> 1, j = cc & 1;
        w = W2[(size_t)(3 * c + 1 + j) * NHID + k];
    }
    __nv_bfloat16 hi = __float2bfloat16_rn(w);
    g_Bh[idx] = hi;
    g_Bl[idx] = __float2bfloat16_rn(w - __bfloat162float(hi));
}

// ---------------------------------------------------------------------------
// k_gemm: cross-block software pipeline. MMA(bi) runs with the softmax math
// of block bi-1 interleaved (register-resident acc_prev); epilogue phase is
// pure STS of (u,v) pairs; copy-out reconstructs w = 1-u-v.
// ---------------------------------------------------------------------------
#define LDA  136
#define LDCB 72                // Cbuf stride (floats): conflict-free STS.64

#define OFF_AH 0
#define OFF_AL 34816
#define OFF_BH 69632
#define OFF_BL 87040
#define SMEM_DYN 106496        // Cbuf 128x72 f32 = 36864 overlays B + 2K

extern "C" __global__ void __launch_bounds__(256, 2)
k_gemm(float* __restrict__ out) {
    extern __shared__ char sm[];
    float* Cbuf = (float*)(sm + OFF_BH);

    const int tid   = threadIdx.x;
    const int wid   = tid >> 5;
    const int lid   = tid & 31;
    const int rbase = blockIdx.y * 128;

    const uint32_t smB = smem_u32(sm);

    // B-staging slot
    const int sb_row = tid >> 2;
    const int sb_q   = (tid & 3) * 4;
    const uint32_t bStsH = smB + OFF_BH + (sb_row * LDA + sb_q * 8) * 2;
    const uint32_t bStsL = smB + OFF_BL + (sb_row * LDA + sb_q * 8) * 2;

    // --- prologue: cp.async stage A (hi+lo) + B(blk 0) ---
    {
        const int sa_row = tid >> 1;
        const int sa_q   = (tid & 1) * 8;
        const char* aH = (const char*)(g_Ah + (size_t)(rbase + sa_row) * NHID);
        const char* aL = (const char*)(g_Al + (size_t)(rbase + sa_row) * NHID);
        #pragma unroll
        for (int q = 0; q < 8; q++) {
            const int qq = sa_q + q;
            cp16(smB + OFF_AH + (sa_row * LDA + qq * 8) * 2, aH + qq * 16);
            cp16(smB + OFF_AL + (sa_row * LDA + qq * 8) * 2, aL + qq * 16);
        }
        const int cc0 = blockIdx.x * 64;
        const uint4* bH = (const uint4*)(g_Bh + (size_t)(cc0 + sb_row) * NHID);
        const uint4* bL = (const uint4*)(g_Bl + (size_t)(cc0 + sb_row) * NHID);
        #pragma unroll
        for (int q = 0; q < 4; q++) {
            cp16(bStsH + q * 16, bH + sb_q + q);
            cp16(bStsL + q * 16, bL + sb_q + q);
        }
        cp_commit();
    }

    const int wr = (wid >> 1) * 32;
    const int wc = (wid & 1)  * 32;

    const int g8 = lid & 7, q4 = lid >> 3;
    const int a_row  = g8 + ((q4 & 1) << 3);
    const int a_koff = (q4 >> 1) << 3;
    const int b_row  = g8 + ((q4 >> 1) << 3);
    const int b_koff = (q4 & 1) << 3;

    uint32_t aAddrH[2], aAddrL[2];
    #pragma unroll
    for (int mi = 0; mi < 2; mi++) {
        const uint32_t off = ((wr + mi * 16 + a_row) * LDA + a_koff) * 2;
        aAddrH[mi] = smB + OFF_AH + off;
        aAddrL[mi] = smB + OFF_AL + off;
    }
    uint32_t bAddrH[2], bAddrL[2];
    #pragma unroll
    for (int np = 0; np < 2; np++) {
        const uint32_t off = ((wc + np * 16 + b_row) * LDA + b_koff) * 2;
        bAddrH[np] = smB + OFF_BH + off;
        bAddrL[np] = smB + OFF_BL + off;
    }

    const int g = lid >> 2, tg = lid & 3;

    float  acc_prev[2][4][4];
    float2 bp_prev[4];
    int    prev_cb = 0;

    for (int bi = 0; bi < 9; bi++) {
        const int blk = bi * CTAX + blockIdx.x;
        if (blk >= NBLK) break;
        const int cb = blk * 32;

        cp_wait0();
        __syncthreads();                 // B(bi) visible; Cbuf free

        // biases for CURRENT block (consumed next iteration)
        float2 bp_cur[4];
        #pragma unroll
        for (int ni = 0; ni < 4; ni++) {
            int cl = cb + ((wc + ni * 8) >> 1) + tg;
            bp_cur[ni] = g_b2p[cl < NCLUST ? cl : (NCLUST - 1)];
        }

        // --- MMA(bi) with interleaved epilogue math of block bi-1 ---
        float acc[2][4][4];
        #pragma unroll
        for (int mi = 0; mi < 2; mi++)
            #pragma unroll
            for (int ni = 0; ni < 4; ni++)
                #pragma unroll
                for (int r = 0; r < 4; r++) acc[mi][ni][r] = 0.0f;

        #pragma unroll
        for (int ks = 0; ks < 8; ks++) {
            const uint32_t kb = ks * 32;
            uint32_t ah[2][4], al[2][4], bh[4][2], bl[4][2];
            #pragma unroll
            for (int mi = 0; mi < 2; mi++) {
                ldsm_x4(ah[mi][0], ah[mi][1], ah[mi][2], ah[mi][3], aAddrH[mi] + kb);
                ldsm_x4(al[mi][0], al[mi][1], al[mi][2], al[mi][3], aAddrL[mi] + kb);
            }
            #pragma unroll
            for (int np = 0; np < 2; np++) {
                ldsm_x4(bh[2*np][0], bh[2*np][1], bh[2*np+1][0], bh[2*np+1][1],
                        bAddrH[np] + kb);
                ldsm_x4(bl[2*np][0], bl[2*np][1], bl[2*np+1][0], bl[2*np+1][1],
                        bAddrL[np] + kb);
            }
            #pragma unroll
            for (int mi = 0; mi < 2; mi++)
                #pragma unroll
                for (int ni = 0; ni < 4; ni++)
                    mma16816(acc[mi][ni], ah[mi], bh[ni]);
            #pragma unroll
            for (int mi = 0; mi < 2; mi++)
                #pragma unroll
                for (int ni = 0; ni < 4; ni++)
                    mma16816(acc[mi][ni], ah[mi], bl[ni]);
            #pragma unroll
            for (int mi = 0; mi < 2; mi++)
                #pragma unroll
                for (int ni = 0; ni < 4; ni++)
                    mma16816(acc[mi][ni], al[mi], bh[ni]);

            // 2 softmax items of block bi-1 (independent of this MMA)
            if (bi > 0) {
                #pragma unroll
                for (int jj = 0; jj < 2; jj++) {
                    const int j   = ks * 2 + jj;
                    const int mi_ = j >> 3;
                    const int ni_ = (j >> 1) & 3;
                    const int rp_ = j & 1;
                    float* s = acc_prev[mi_][ni_];
                    float e1 = fexp(s[2 * rp_]     + bp_prev[ni_].x);
                    float e2 = fexp(s[2 * rp_ + 1] + bp_prev[ni_].y);
                    float inv = frcp(1.0f + e1 + e2);
                    s[2 * rp_]     = e1 * inv;
                    s[2 * rp_ + 1] = e2 * inv;
                }
            }
        }
        __syncthreads();                 // B consumed -> Cbuf may overwrite

        // --- STS (u,v) pairs of block bi-1 into Cbuf ---
        if (bi > 0) {
            #pragma unroll
            for (int mi = 0; mi < 2; mi++) {
                const int r0 = wr + mi * 16 + g;
                #pragma unroll
                for (int ni = 0; ni < 4; ni++) {
                    const int cl_loc = ((wc + ni * 8) >> 1) + tg;
                    *(float2*)(Cbuf + r0 * LDCB + 2 * cl_loc) =
                        *(float2*)&acc_prev[mi][ni][0];
                    *(float2*)(Cbuf + (r0 + 8) * LDCB + 2 * cl_loc) =
                        *(float2*)&acc_prev[mi][ni][2];
                }
            }
        }
        __syncthreads();                 // Cbuf complete

        // --- copy-out block bi-1 (reconstruct w = 1-u-v) ---
        if (bi > 0) {
            if (prev_cb + 32 <= NCLUST) {
                #pragma unroll
                for (int t = tid; t < 128 * 8; t += 256) {
                    const int lr = t >> 3, s = t & 7;
                    const float4 p0 = *(float4*)(Cbuf + lr * LDCB + 8 * s);
                    const float4 p1 = *(float4*)(Cbuf + lr * LDCB + 8 * s + 4);
                    float w0 = 1.0f - p0.x - p0.y;
                    float w1 = 1.0f - p0.z - p0.w;
                    float w2 = 1.0f - p1.x - p1.y;
                    float w3 = 1.0f - p1.z - p1.w;
                    float* dst = out + (size_t)(rbase + lr) * NOUT + 3 * prev_cb + 12 * s;
                    __stcs((float4*)dst,       make_float4(w0, p0.x, p0.y, w1));
                    __stcs((float4*)(dst + 4), make_float4(p0.z, p0.w, w2, p1.x));
                    __stcs((float4*)(dst + 8), make_float4(p1.y, w3, p1.z, p1.w));
                }
            } else {
                for (int t = tid; t < 128 * 4; t += 256) {
                    const int lr = t >> 2, s = t & 3;
                    const float4 p0 = *(float4*)(Cbuf + lr * LDCB + 8 * s);
                    const float4 p1 = *(float4*)(Cbuf + lr * LDCB + 8 * s + 4);
                    float w0 = 1.0f - p0.x - p0.y;
                    float w1 = 1.0f - p0.z - p0.w;
                    float w2 = 1.0f - p1.x - p1.y;
                    float w3 = 1.0f - p1.z - p1.w;
                    float* dst = out + (size_t)(rbase + lr) * NOUT + 3 * prev_cb + 12 * s;
                    __stcs((float4*)dst,       make_float4(w0, p0.x, p0.y, w1));
                    __stcs((float4*)(dst + 4), make_float4(p0.z, p0.w, w2, p1.x));
                    __stcs((float4*)(dst + 8), make_float4(p1.y, w3, p1.z, p1.w));
                }
            }
        }
        __syncthreads();                 // Cbuf/B region free

        // --- stage B(bi+1) via cp.async into B region ---
        const int nblk = (bi + 1) * CTAX + blockIdx.x;
        if (nblk < NBLK) {
            const int cc0 = nblk * 64;
            const uint4* bH = (const uint4*)(g_Bh + (size_t)(cc0 + sb_row) * NHID);
            const uint4* bL = (const uint4*)(g_Bl + (size_t)(cc0 + sb_row) * NHID);
            #pragma unroll
            for (int q = 0; q < 4; q++) {
                cp16(bStsH + q * 16, bH + sb_q + q);
                cp16(bStsL + q * 16, bL + sb_q + q);
            }
            cp_commit();
        }

        // rotate pipeline state
        #pragma unroll
        for (int mi = 0; mi < 2; mi++)
            #pragma unroll
            for (int ni = 0; ni < 4; ni++)
                #pragma unroll
                for (int r = 0; r < 4; r++)
                    acc_prev[mi][ni][r] = acc[mi][ni][r];
        #pragma unroll
        for (int ni = 0; ni < 4; ni++) bp_prev[ni] = bp_cur[ni];
        prev_cb = cb;
    }

    // --- tail: epilogue + output of the final block ---
    {
        #pragma unroll
        for (int j = 0; j < 16; j++) {
            const int mi_ = j >> 3;
            const int ni_ = (j >> 1) & 3;
            const int rp_ = j & 1;
            float* s = acc_prev[mi_][ni_];
            float e1 = fexp(s[2 * rp_]     + bp_prev[ni_].x);
            float e2 = fexp(s[2 * rp_ + 1] + bp_prev[ni_].y);
            float inv = frcp(1.0f + e1 + e2);
            s[2 * rp_]     = e1 * inv;
            s[2 * rp_ + 1] = e2 * inv;
        }
        #pragma unroll
        for (int mi = 0; mi < 2; mi++) {
            const int r0 = wr + mi * 16 + g;
            #pragma unroll
            for (int ni = 0; ni < 4; ni++) {
                const int cl_loc = ((wc + ni * 8) >> 1) + tg;
                *(float2*)(Cbuf + r0 * LDCB + 2 * cl_loc) =
                    *(float2*)&acc_prev[mi][ni][0];
                *(float2*)(Cbuf + (r0 + 8) * LDCB + 2 * cl_loc) =
                    *(float2*)&acc_prev[mi][ni][2];
            }
        }
        __syncthreads();

        if (prev_cb + 32 <= NCLUST) {
            #pragma unroll
            for (int t = tid; t < 128 * 8; t += 256) {
                const int lr = t >> 3, s = t & 7;
                const float4 p0 = *(float4*)(Cbuf + lr * LDCB + 8 * s);
                const float4 p1 = *(float4*)(Cbuf + lr * LDCB + 8 * s + 4);
                float w0 = 1.0f - p0.x - p0.y;
                float w1 = 1.0f - p0.z - p0.w;
                float w2 = 1.0f - p1.x - p1.y;
                float w3 = 1.0f - p1.z - p1.w;
                float* dst = out + (size_t)(rbase + lr) * NOUT + 3 * prev_cb + 12 * s;
                __stcs((float4*)dst,       make_float4(w0, p0.x, p0.y, w1));
                __stcs((float4*)(dst + 4), make_float4(p0.z, p0.w, w2, p1.x));
                __stcs((float4*)(dst + 8), make_float4(p1.y, w3, p1.z, p1.w));
            }
        } else {
            for (int t = tid; t < 128 * 4; t += 256) {
                const int lr = t >> 2, s = t & 3;
                const float4 p0 = *(float4*)(Cbuf + lr * LDCB + 8 * s);
                const float4 p1 = *(float4*)(Cbuf + lr * LDCB + 8 * s + 4);
                float w0 = 1.0f - p0.x - p0.y;
                float w1 = 1.0f - p0.z - p0.w;
                float w2 = 1.0f - p1.x - p1.y;
                float w3 = 1.0f - p1.z - p1.w;
                float* dst = out + (size_t)(rbase + lr) * NOUT + 3 * prev_cb + 12 * s;
                __stcs((float4*)dst,       make_float4(w0, p0.x, p0.y, w1));
                __stcs((float4*)(dst + 4), make_float4(p0.z, p0.w, w2, p1.x));
                __stcs((float4*)(dst + 8), make_float4(p1.y, w3, p1.z, p1.w));
            }
        }
    }
}

// ---------------------------------------------------------------------------
extern "C" void kernel_launch(void* const* d_in, const int* in_sizes, int n_in,
                              void* d_out, int out_size) {
    const float* z     = (const float*)d_in[0];
    const float* W1    = (const float*)d_in[1];
    const float* b1    = (const float*)d_in[2];
    const float* gamma = (const float*)d_in[3];
    const float* beta  = (const float*)d_in[4];
    const float* W2    = (const float*)d_in[5];
    const float* b2    = (const float*)d_in[6];
    float* out = (float*)d_out;

    k_init<<<1, 128>>>();
    k_h<<<BATCH / 128, 256>>>(z, W1, b1);
    k_bn<<<1, 128>>>(gamma, beta);
    k_split_h<<<(BATCH * NHID + 255) / 256, 256>>>();
    k_split_w<<<(NCC_PAD * NHID + 255) / 256, 256>>>(W2, b2);

    cudaFuncSetAttribute(k_gemm, cudaFuncAttributeMaxDynamicSharedMemorySize,
                         SMEM_DYN);
    dim3 grid(CTAX, BATCH / 128);   // (37, 32) = 1184 CTAs = 4 waves
    k_gemm<<<grid, 256, SMEM_DYN>>>(out);
}

// round 15
// speedup vs baseline: 1.0822x; 1.0822x over previous
#include <cuda_runtime.h>
#include <cuda_bf16.h>
#include <math.h>
#include <cstdint>

#define BATCH  4096
#define NIN    32
#define NHID   128
#define NOUT   30000
#define NCLUST 10000
#define BN_EPS 1e-3f

#define NCC      20000
#define NCC_PAD  20480
#define NBLK     313
#define CTAX     37            // 1184 CTAs = exactly 4 waves @ occ 2

// ---- scratch ----
__device__ float g_h[BATCH * NHID];
__device__ float g_sum[NHID];
__device__ float g_sumsq[NHID];
__device__ float g_scale[NHID];
__device__ float g_shift[NHID];
__device__ __nv_bfloat16 g_Ah[BATCH * NHID];
__device__ __nv_bfloat16 g_Al[BATCH * NHID];
__device__ __nv_bfloat16 g_Bh[NCC_PAD * NHID];
__device__ __nv_bfloat16 g_Bl[NCC_PAD * NHID];
__device__ float2 g_b2p[10240];

// ---- MUFU-free exp / rcp ----------------------------------------------------
__device__ __forceinline__ float fexp(float x) {
    float t  = x * 1.4426950408889634f;
    float rf = t + 12582912.0f;
    int   ri = __float_as_int(rf) - 0x4B400000;
    float f  = t - (rf - 12582912.0f);
    float p = 1.3333558e-3f;
    p = fmaf(p, f, 9.6181291e-3f);
    p = fmaf(p, f, 5.5504109e-2f);
    p = fmaf(p, f, 2.4022651e-1f);
    p = fmaf(p, f, 6.9314718e-1f);
    p = fmaf(p, f, 1.0f);
    return __int_as_float(__float_as_int(p) + (ri << 23));
}
__device__ __forceinline__ float frcp(float d) {
    float r = __int_as_float(0x7EF127EAu - __float_as_int(d));
    #pragma unroll
    for (int i = 0; i < 2; i++) {
        float e = fmaf(-d, r, 1.0f);
        r = fmaf(r, e, r);
    }
    return r;
}

__device__ __forceinline__ uint32_t smem_u32(const void* p) {
    uint32_t a;
    asm("{ .reg .u64 t; cvta.to.shared.u64 t, %1; cvt.u32.u64 %0, t; }"
        : "=r"(a) : "l"(p));
    return a;
}
__device__ __forceinline__ void cp16(uint32_t dst, const void* src) {
    asm volatile("cp.async.cg.shared.global [%0], [%1], 16;"
                 :: "r"(dst), "l"(src));
}
__device__ __forceinline__ void cp_commit() {
    asm volatile("cp.async.commit_group;");
}
__device__ __forceinline__ void cp_wait0() {
    asm volatile("cp.async.wait_group 0;");
}
__device__ __forceinline__ void ldsm_x4(uint32_t& r0, uint32_t& r1,
                                        uint32_t& r2, uint32_t& r3, uint32_t a) {
    asm volatile("ldmatrix.sync.aligned.m8n8.x4.shared.b16 {%0,%1,%2,%3}, [%4];"
                 : "=r"(r0), "=r"(r1), "=r"(r2), "=r"(r3) : "r"(a));
}
__device__ __forceinline__ void mma16816(float* c, const uint32_t* a,
                                         const uint32_t* b) {
    asm volatile("mma.sync.aligned.m16n8k16.row.col.f32.bf16.bf16.f32 "
                 "{%0,%1,%2,%3}, {%4,%5,%6,%7}, {%8,%9}, {%0,%1,%2,%3};"
                 : "+f"(c[0]), "+f"(c[1]), "+f"(c[2]), "+f"(c[3])
                 : "r"(a[0]), "r"(a[1]), "r"(a[2]), "r"(a[3]),
                   "r"(b[0]), "r"(b[1]));
}

// ---------------------------------------------------------------------------
__global__ void k_init() {
    int i = threadIdx.x;
    if (i < NHID) { g_sum[i] = 0.0f; g_sumsq[i] = 0.0f; }
}

__global__ void k_h(const float* __restrict__ z,
                    const float* __restrict__ W1,
                    const float* __restrict__ b1) {
    __shared__ float zs[128][33];
    __shared__ float ws[128][33];
    __shared__ float ps[2][128];
    __shared__ float psq[2][128];

    const int tid   = threadIdx.x;
    const int rbase = blockIdx.x * 128;

    for (int idx = tid; idx < 128 * NIN; idx += 256) {
        int r = idx >> 5, k = idx & 31;
        zs[r][k] = z[(rbase + r) * NIN + k];
        ws[r][k] = W1[idx];
    }
    __syncthreads();

    const int col = tid & 127;
    const int rh  = tid >> 7;
    const float bb = b1[col];
    float ls = 0.0f, lsq = 0.0f;

    for (int r = rh * 64; r < rh * 64 + 64; r++) {
        float acc = bb;
        #pragma unroll
        for (int k = 0; k < NIN; k++)
            acc = fmaf(zs[r][k], ws[col][k], acc);
        g_h[(rbase + r) * NHID + col] = acc;
        ls += acc;
        lsq = fmaf(acc, acc, lsq);
    }
    ps[rh][col]  = ls;
    psq[rh][col] = lsq;
    __syncthreads();
    if (tid < 128) {
        atomicAdd(&g_sum[tid],   ps[0][tid]  + ps[1][tid]);
        atomicAdd(&g_sumsq[tid], psq[0][tid] + psq[1][tid]);
    }
}

__global__ void k_bn(const float* __restrict__ gamma,
                     const float* __restrict__ beta) {
    int c = threadIdx.x;
    if (c >= NHID) return;
    const float inv_b = 1.0f / (float)BATCH;
    float mu   = g_sum[c] * inv_b;
    float var  = g_sumsq[c] * inv_b - mu * mu;
    float rstd = rsqrtf(var + BN_EPS);
    float sc   = gamma[c] * rstd;
    g_scale[c] = sc;
    g_shift[c] = beta[c] - mu * sc;
}

// merged split kernel: blocks [0,2048) -> A split; [2048,12288) -> W2 split
#define SPLIT_HBLK 2048
__global__ void k_split(const float* __restrict__ W2,
                        const float* __restrict__ b2) {
    const int b = blockIdx.x;
    if (b < SPLIT_HBLK) {
        const int idx = b * 256 + threadIdx.x;
        const int k = idx & 127;
        float v = fmaxf(fmaf(g_h[idx], g_scale[k], g_shift[k]), 0.0f);
        __nv_bfloat16 hi = __float2bfloat16_rn(v);
        g_Ah[idx] = hi;
        g_Al[idx] = __float2bfloat16_rn(v - __bfloat162float(hi));
    } else {
        const int idx = (b - SPLIT_HBLK) * 256 + threadIdx.x;
        if (idx < 10240) {
            float2 bp = make_float2(0.0f, 0.0f);
            if (idx < NCLUST)
                bp = make_float2(b2[3 * idx + 1], b2[3 * idx + 2]);
            g_b2p[idx] = bp;
        }
        const int cc = idx >> 7;
        const int k  = idx & 127;
        float w = 0.0f;
        if (cc < NCC) {
            const int c = cc >> 1, j = cc & 1;
            w = W2[(size_t)(3 * c + 1 + j) * NHID + k];
        }
        __nv_bfloat16 hi = __float2bfloat16_rn(w);
        g_Bh[idx] = hi;
        g_Bl[idx] = __float2bfloat16_rn(w - __bfloat162float(hi));
    }
}

// ---------------------------------------------------------------------------
// k_gemm: R12 skeleton + (u,v)-compressed single-pass epilogue (4 barriers
// per block) + w = 1-u-v reconstruction in the coalesced copy-out.
// ---------------------------------------------------------------------------
#define LDA  136
#define LDCB 72                // Cbuf stride (floats); 2-way worst STS conflict

#define OFF_AH 0
#define OFF_AL 34816
#define OFF_BH 69632
#define OFF_BL 87040
#define SMEM_DYN 106496        // Cbuf 128x72 f32 = 36864 overlays B region

extern "C" __global__ void __launch_bounds__(256, 2)
k_gemm(float* __restrict__ out) {
    extern __shared__ char sm[];
    float* Cbuf = (float*)(sm + OFF_BH);

    const int tid   = threadIdx.x;
    const int wid   = tid >> 5;
    const int lid   = tid & 31;
    const int rbase = blockIdx.y * 128;

    const uint32_t smB = smem_u32(sm);

    // B-staging slot: 64 rows x 16 quads per array, 4 quads/thread
    const int sb_row = tid >> 2;
    const int sb_q   = (tid & 3) * 4;
    const uint32_t bStsH = smB + OFF_BH + (sb_row * LDA + sb_q * 8) * 2;
    const uint32_t bStsL = smB + OFF_BL + (sb_row * LDA + sb_q * 8) * 2;

    // --- prologue: cp.async stage A (hi+lo) + B(blk 0) ---
    {
        const int sa_row = tid >> 1;
        const int sa_q   = (tid & 1) * 8;
        const char* aH = (const char*)(g_Ah + (size_t)(rbase + sa_row) * NHID);
        const char* aL = (const char*)(g_Al + (size_t)(rbase + sa_row) * NHID);
        #pragma unroll
        for (int q = 0; q < 8; q++) {
            const int qq = sa_q + q;
            cp16(smB + OFF_AH + (sa_row * LDA + qq * 8) * 2, aH + qq * 16);
            cp16(smB + OFF_AL + (sa_row * LDA + qq * 8) * 2, aL + qq * 16);
        }
        const int cc0 = blockIdx.x * 64;
        const uint4* bH = (const uint4*)(g_Bh + (size_t)(cc0 + sb_row) * NHID);
        const uint4* bL = (const uint4*)(g_Bl + (size_t)(cc0 + sb_row) * NHID);
        #pragma unroll
        for (int q = 0; q < 4; q++) {
            cp16(bStsH + q * 16, bH + sb_q + q);
            cp16(bStsL + q * 16, bL + sb_q + q);
        }
        cp_commit();
    }

    const int wr = (wid >> 1) * 32;
    const int wc = (wid & 1)  * 32;

    const int g8 = lid & 7, q4 = lid >> 3;
    const int a_row  = g8 + ((q4 & 1) << 3);
    const int a_koff = (q4 >> 1) << 3;
    const int b_row  = g8 + ((q4 >> 1) << 3);
    const int b_koff = (q4 & 1) << 3;

    uint32_t aAddrH[2], aAddrL[2];
    #pragma unroll
    for (int mi = 0; mi < 2; mi++) {
        const uint32_t off = ((wr + mi * 16 + a_row) * LDA + a_koff) * 2;
        aAddrH[mi] = smB + OFF_AH + off;
        aAddrL[mi] = smB + OFF_AL + off;
    }
    uint32_t bAddrH[2], bAddrL[2];
    #pragma unroll
    for (int np = 0; np < 2; np++) {
        const uint32_t off = ((wc + np * 16 + b_row) * LDA + b_koff) * 2;
        bAddrH[np] = smB + OFF_BH + off;
        bAddrL[np] = smB + OFF_BL + off;
    }

    const int g = lid >> 2, tg = lid & 3;

    cp_wait0();                          // prologue staging complete

    for (int bi = 0; bi < 9; bi++) {
        const int blk = bi * CTAX + blockIdx.x;
        if (blk >= NBLK) break;
        const int cb = blk * 32;

        __syncthreads();                 // staged B visible (prologue or STS)

        // --- register-prefetch NEXT block's B ---
        const int nblk = (bi + 1) * CTAX + blockIdx.x;
        const int pcc0 = (nblk < NBLK ? nblk : 0) * 64;
        uint4 pfh[4], pfl[4];
        {
            const uint4* bH = (const uint4*)(g_Bh + (size_t)(pcc0 + sb_row) * NHID);
            const uint4* bL = (const uint4*)(g_Bl + (size_t)(pcc0 + sb_row) * NHID);
            #pragma unroll
            for (int q = 0; q < 4; q++) {
                pfh[q] = __ldg(bH + sb_q + q);
                pfl[q] = __ldg(bL + sb_q + q);
            }
        }

        // prefetch biases for this thread's 4 clusters
        float2 bp[4];
        #pragma unroll
        for (int ni = 0; ni < 4; ni++) {
            int cl = cb + ((wc + ni * 8) >> 1) + tg;
            bp[ni] = g_b2p[cl < NCLUST ? cl : (NCLUST - 1)];
        }

        // --- MMA: acc[mi][ni][4], chain-major over 8 independent accs ---
        float acc[2][4][4];
        #pragma unroll
        for (int mi = 0; mi < 2; mi++)
            #pragma unroll
            for (int ni = 0; ni < 4; ni++)
                #pragma unroll
                for (int r = 0; r < 4; r++) acc[mi][ni][r] = 0.0f;

        #pragma unroll
        for (int ks = 0; ks < 8; ks++) {
            const uint32_t kb = ks * 32;
            uint32_t ah[2][4], al[2][4], bh[4][2], bl[4][2];
            #pragma unroll
            for (int mi = 0; mi < 2; mi++) {
                ldsm_x4(ah[mi][0], ah[mi][1], ah[mi][2], ah[mi][3], aAddrH[mi] + kb);
                ldsm_x4(al[mi][0], al[mi][1], al[mi][2], al[mi][3], aAddrL[mi] + kb);
            }
            #pragma unroll
            for (int np = 0; np < 2; np++) {
                ldsm_x4(bh[2*np][0], bh[2*np][1], bh[2*np+1][0], bh[2*np+1][1],
                        bAddrH[np] + kb);
                ldsm_x4(bl[2*np][0], bl[2*np][1], bl[2*np+1][0], bl[2*np+1][1],
                        bAddrL[np] + kb);
            }
            #pragma unroll
            for (int mi = 0; mi < 2; mi++)
                #pragma unroll
                for (int ni = 0; ni < 4; ni++)
                    mma16816(acc[mi][ni], ah[mi], bh[ni]);
            #pragma unroll
            for (int mi = 0; mi < 2; mi++)
                #pragma unroll
                for (int ni = 0; ni < 4; ni++)
                    mma16816(acc[mi][ni], ah[mi], bl[ni]);
            #pragma unroll
            for (int mi = 0; mi < 2; mi++)
                #pragma unroll
                for (int ni = 0; ni < 4; ni++)
                    mma16816(acc[mi][ni], al[mi], bh[ni]);
        }
        __syncthreads();                 // B consumed -> Cbuf may overwrite

        // --- single-pass epilogue: softmax -> (u,v) float2 in Cbuf ---
        #pragma unroll
        for (int mi = 0; mi < 2; mi++) {
            const int r0 = wr + mi * 16 + g;
            #pragma unroll
            for (int ni = 0; ni < 4; ni++) {
                const int cl_loc = ((wc + ni * 8) >> 1) + tg;
                float e1 = fexp(acc[mi][ni][0] + bp[ni].x);
                float e2 = fexp(acc[mi][ni][1] + bp[ni].y);
                float inv = frcp(1.0f + e1 + e2);
                *(float2*)(Cbuf + r0 * LDCB + 2 * cl_loc) =
                    make_float2(e1 * inv, e2 * inv);
                e1 = fexp(acc[mi][ni][2] + bp[ni].x);
                e2 = fexp(acc[mi][ni][3] + bp[ni].y);
                inv = frcp(1.0f + e1 + e2);
                *(float2*)(Cbuf + (r0 + 8) * LDCB + 2 * cl_loc) =
                    make_float2(e1 * inv, e2 * inv);
            }
        }
        __syncthreads();                 // Cbuf complete

        // --- copy-out: reconstruct w = 1-u-v, dense __stcs stores ---
        if (cb + 32 <= NCLUST) {
            #pragma unroll
            for (int t = tid; t < 128 * 8; t += 256) {
                const int lr = t >> 3, s = t & 7;
                const float4 p0 = *(float4*)(Cbuf + lr * LDCB + 8 * s);
                const float4 p1 = *(float4*)(Cbuf + lr * LDCB + 8 * s + 4);
                float w0 = 1.0f - p0.x - p0.y;
                float w1 = 1.0f - p0.z - p0.w;
                float w2 = 1.0f - p1.x - p1.y;
                float w3 = 1.0f - p1.z - p1.w;
                float* dst = out + (size_t)(rbase + lr) * NOUT + 3 * cb + 12 * s;
                __stcs((float4*)dst,       make_float4(w0, p0.x, p0.y, w1));
                __stcs((float4*)(dst + 4), make_float4(p0.z, p0.w, w2, p1.x));
                __stcs((float4*)(dst + 8), make_float4(p1.y, w3, p1.z, p1.w));
            }
        } else {
            for (int t = tid; t < 128 * 4; t += 256) {
                const int lr = t >> 2, s = t & 3;
                const float4 p0 = *(float4*)(Cbuf + lr * LDCB + 8 * s);
                const float4 p1 = *(float4*)(Cbuf + lr * LDCB + 8 * s + 4);
                float w0 = 1.0f - p0.x - p0.y;
                float w1 = 1.0f - p0.z - p0.w;
                float w2 = 1.0f - p1.x - p1.y;
                float w3 = 1.0f - p1.z - p1.w;
                float* dst = out + (size_t)(rbase + lr) * NOUT + 3 * cb + 12 * s;
                __stcs((float4*)dst,       make_float4(w0, p0.x, p0.y, w1));
                __stcs((float4*)(dst + 4), make_float4(p0.z, p0.w, w2, p1.x));
                __stcs((float4*)(dst + 8), make_float4(p1.y, w3, p1.z, p1.w));
            }
        }
        __syncthreads();                 // Cbuf/B region free

        // --- STS prefetched next-B into B region ---
        if (nblk < NBLK) {
            #pragma unroll
            for (int q = 0; q < 4; q++) {
                *(uint4*)(sm + (bStsH - smB) + q * 16) = pfh[q];
                *(uint4*)(sm + (bStsL - smB) + q * 16) = pfl[q];
            }
        }
    }
}

// ---------------------------------------------------------------------------
extern "C" void kernel_launch(void* const* d_in, const int* in_sizes, int n_in,
                              void* d_out, int out_size) {
    const float* z     = (const float*)d_in[0];
    const float* W1    = (const float*)d_in[1];
    const float* b1    = (const float*)d_in[2];
    const float* gamma = (const float*)d_in[3];
    const float* beta  = (const float*)d_in[4];
    const float* W2    = (const float*)d_in[5];
    const float* b2    = (const float*)d_in[6];
    float* out = (float*)d_out;

    k_init<<<1, 128>>>();
    k_h<<<BATCH / 128, 256>>>(z, W1, b1);
    k_bn<<<1, 128>>>(gamma, beta);
    k_split<<<SPLIT_HBLK + NCC_PAD * NHID / 256, 256>>>(W2, b2);

    cudaFuncSetAttribute(k_gemm, cudaFuncAttributeMaxDynamicSharedMemorySize,
                         SMEM_DYN);
    dim3 grid(CTAX, BATCH / 128);   // (37, 32) = 1184 CTAs = 4 waves
    k_gemm<<<grid, 256, SMEM_DYN>>>(out);
}

// round 16
// speedup vs baseline: 1.4912x; 1.3779x over previous
#include <cuda_runtime.h>
#include <cuda_fp16.h>
#include <math.h>
#include <cstdint>

#define BATCH  4096
#define NIN    32
#define NHID   128
#define NOUT   30000
#define NCLUST 10000
#define BN_EPS 1e-3f

#define NCC      20000
#define NCC_PAD  20480
#define NBLK     313
#define CTAX     41            // 1312 CTAs = 2.95 waves @ occ 3

// ---- scratch ----
__device__ float g_h[BATCH * NHID];
__device__ float g_sum[NHID];
__device__ float g_sumsq[NHID];
__device__ float g_scale[NHID];
__device__ float g_shift[NHID];
__device__ __half g_Ah[BATCH * NHID];          // fp16 hi only
__device__ __half g_Bh[NCC_PAD * NHID];        // fp16 hi
__device__ __half g_Bl[NCC_PAD * NHID];        // fp16 lo
__device__ float2 g_b2p[10240];

// ---- MUFU-free exp / rcp ----------------------------------------------------
__device__ __forceinline__ float fexp(float x) {
    float t  = x * 1.4426950408889634f;
    float rf = t + 12582912.0f;
    int   ri = __float_as_int(rf) - 0x4B400000;
    float f  = t - (rf - 12582912.0f);
    float p = 1.3333558e-3f;
    p = fmaf(p, f, 9.6181291e-3f);
    p = fmaf(p, f, 5.5504109e-2f);
    p = fmaf(p, f, 2.4022651e-1f);
    p = fmaf(p, f, 6.9314718e-1f);
    p = fmaf(p, f, 1.0f);
    return __int_as_float(__float_as_int(p) + (ri << 23));
}
__device__ __forceinline__ float frcp(float d) {
    float r = __int_as_float(0x7EF127EAu - __float_as_int(d));
    #pragma unroll
    for (int i = 0; i < 2; i++) {
        float e = fmaf(-d, r, 1.0f);
        r = fmaf(r, e, r);
    }
    return r;
}

__device__ __forceinline__ uint32_t smem_u32(const void* p) {
    uint32_t a;
    asm("{ .reg .u64 t; cvta.to.shared.u64 t, %1; cvt.u32.u64 %0, t; }"
        : "=r"(a) : "l"(p));
    return a;
}
__device__ __forceinline__ void cp16(uint32_t dst, const void* src) {
    asm volatile("cp.async.cg.shared.global [%0], [%1], 16;"
                 :: "r"(dst), "l"(src));
}
__device__ __forceinline__ void cp_commit() {
    asm volatile("cp.async.commit_group;");
}
__device__ __forceinline__ void cp_wait0() {
    asm volatile("cp.async.wait_group 0;");
}
__device__ __forceinline__ void ldsm_x4(uint32_t& r0, uint32_t& r1,
                                        uint32_t& r2, uint32_t& r3, uint32_t a) {
    asm volatile("ldmatrix.sync.aligned.m8n8.x4.shared.b16 {%0,%1,%2,%3}, [%4];"
                 : "=r"(r0), "=r"(r1), "=r"(r2), "=r"(r3) : "r"(a));
}
__device__ __forceinline__ void mma16816(float* c, const uint32_t* a,
                                         const uint32_t* b) {
    asm volatile("mma.sync.aligned.m16n8k16.row.col.f32.f16.f16.f32 "
                 "{%0,%1,%2,%3}, {%4,%5,%6,%7}, {%8,%9}, {%0,%1,%2,%3};"
                 : "+f"(c[0]), "+f"(c[1]), "+f"(c[2]), "+f"(c[3])
                 : "r"(a[0]), "r"(a[1]), "r"(a[2]), "r"(a[3]),
                   "r"(b[0]), "r"(b[1]));
}

// ---------------------------------------------------------------------------
__global__ void k_init() {
    int i = threadIdx.x;
    if (i < NHID) { g_sum[i] = 0.0f; g_sumsq[i] = 0.0f; }
}

__global__ void k_h(const float* __restrict__ z,
                    const float* __restrict__ W1,
                    const float* __restrict__ b1) {
    __shared__ float zs[128][33];
    __shared__ float ws[128][33];
    __shared__ float ps[2][128];
    __shared__ float psq[2][128];

    const int tid   = threadIdx.x;
    const int rbase = blockIdx.x * 128;

    for (int idx = tid; idx < 128 * NIN; idx += 256) {
        int r = idx >> 5, k = idx & 31;
        zs[r][k] = z[(rbase + r) * NIN + k];
        ws[r][k] = W1[idx];
    }
    __syncthreads();

    const int col = tid & 127;
    const int rh  = tid >> 7;
    const float bb = b1[col];
    float ls = 0.0f, lsq = 0.0f;

    for (int r = rh * 64; r < rh * 64 + 64; r++) {
        float acc = bb;
        #pragma unroll
        for (int k = 0; k < NIN; k++)
            acc = fmaf(zs[r][k], ws[col][k], acc);
        g_h[(rbase + r) * NHID + col] = acc;
        ls += acc;
        lsq = fmaf(acc, acc, lsq);
    }
    ps[rh][col]  = ls;
    psq[rh][col] = lsq;
    __syncthreads();
    if (tid < 128) {
        atomicAdd(&g_sum[tid],   ps[0][tid]  + ps[1][tid]);
        atomicAdd(&g_sumsq[tid], psq[0][tid] + psq[1][tid]);
    }
}

__global__ void k_bn(const float* __restrict__ gamma,
                     const float* __restrict__ beta) {
    int c = threadIdx.x;
    if (c >= NHID) return;
    const float inv_b = 1.0f / (float)BATCH;
    float mu   = g_sum[c] * inv_b;
    float var  = g_sumsq[c] * inv_b - mu * mu;
    float rstd = rsqrtf(var + BN_EPS);
    float sc   = gamma[c] * rstd;
    g_scale[c] = sc;
    g_shift[c] = beta[c] - mu * sc;
}

// merged split kernel: blocks [0,2048) -> A fp16 hi; rest -> W2 fp16 hi/lo
#define SPLIT_HBLK 2048
__global__ void k_split(const float* __restrict__ W2,
                        const float* __restrict__ b2) {
    const int b = blockIdx.x;
    if (b < SPLIT_HBLK) {
        const int idx = b * 256 + threadIdx.x;
        const int k = idx & 127;
        float v = fmaxf(fmaf(g_h[idx], g_scale[k], g_shift[k]), 0.0f);
        g_Ah[idx] = __float2half_rn(v);
    } else {
        const int idx = (b - SPLIT_HBLK) * 256 + threadIdx.x;
        if (idx < 10240) {
            float2 bp = make_float2(0.0f, 0.0f);
            if (idx < NCLUST)
                bp = make_float2(b2[3 * idx + 1], b2[3 * idx + 2]);
            g_b2p[idx] = bp;
        }
        const int cc = idx >> 7;
        const int k  = idx & 127;
        float w = 0.0f;
        if (cc < NCC) {
            const int c = cc >> 1, j = cc & 1;
            w = W2[(size_t)(3 * c + 1 + j) * NHID + k];
        }
        __half hi = __float2half_rn(w);
        g_Bh[idx] = hi;
        g_Bl[idx] = __float2half_rn(w - __half2float(hi));
    }
}

// ---------------------------------------------------------------------------
// k_gemm: fp16 2-chain (aH*bH + aH*bL), A hi-only resident; occupancy 3.
// R12 epilogue (dense two-pass staged copy-out) unchanged.
// ---------------------------------------------------------------------------
#define LDA  136
#define LDCB 100

#define OFF_AH 0               // 34816 B
#define OFF_BH 34816           // 17408 B
#define OFF_BL 52224           // 17408 B
#define SMEM_DYN 69632         // Cbuf [64][100] f32 = 25600 overlays B region

extern "C" __global__ void __launch_bounds__(256, 3)
k_gemm(float* __restrict__ out) {
    extern __shared__ char sm[];
    float* Cbuf = (float*)(sm + OFF_BH);

    const int tid   = threadIdx.x;
    const int wid   = tid >> 5;
    const int lid   = tid & 31;
    const int rbase = blockIdx.y * 128;

    const uint32_t smB = smem_u32(sm);

    // B-staging slot: 64 rows x 16 quads per array, 4 quads/thread
    const int sb_row = tid >> 2;
    const int sb_q   = (tid & 3) * 4;
    const uint32_t bStsH = smB + OFF_BH + (sb_row * LDA + sb_q * 8) * 2;
    const uint32_t bStsL = smB + OFF_BL + (sb_row * LDA + sb_q * 8) * 2;

    // --- prologue: cp.async stage A(hi) + B(blk 0) ---
    {
        const int sa_row = tid >> 1;          // 0..127
        const int sa_q   = (tid & 1) * 8;
        const char* aH = (const char*)(g_Ah + (size_t)(rbase + sa_row) * NHID);
        #pragma unroll
        for (int q = 0; q < 8; q++) {
            const int qq = sa_q + q;
            cp16(smB + OFF_AH + (sa_row * LDA + qq * 8) * 2, aH + qq * 16);
        }
        const int cc0 = blockIdx.x * 64;
        const uint4* bH = (const uint4*)(g_Bh + (size_t)(cc0 + sb_row) * NHID);
        const uint4* bL = (const uint4*)(g_Bl + (size_t)(cc0 + sb_row) * NHID);
        #pragma unroll
        for (int q = 0; q < 4; q++) {
            cp16(bStsH + q * 16, bH + sb_q + q);
            cp16(bStsL + q * 16, bL + sb_q + q);
        }
        cp_commit();
    }

    const int wr = (wid >> 1) * 32;
    const int wc = (wid & 1)  * 32;

    const int g8 = lid & 7, q4 = lid >> 3;
    const int a_row  = g8 + ((q4 & 1) << 3);
    const int a_koff = (q4 >> 1) << 3;
    const int b_row  = g8 + ((q4 >> 1) << 3);
    const int b_koff = (q4 & 1) << 3;

    uint32_t aAddrH[2];
    #pragma unroll
    for (int mi = 0; mi < 2; mi++)
        aAddrH[mi] = smB + OFF_AH + ((wr + mi * 16 + a_row) * LDA + a_koff) * 2;
    uint32_t bAddrH[2], bAddrL[2];
    #pragma unroll
    for (int np = 0; np < 2; np++) {
        const uint32_t off = ((wc + np * 16 + b_row) * LDA + b_koff) * 2;
        bAddrH[np] = smB + OFF_BH + off;
        bAddrL[np] = smB + OFF_BL + off;
    }

    const int g = lid >> 2, tg = lid & 3;
    const int lrow0 = (wr >> 1) + g;

    const int nbi = (NBLK + CTAX - 1) / CTAX;   // 8

    for (int bi = 0; bi < nbi; bi++) {
        const int blk = bi * CTAX + blockIdx.x;
        if (blk >= NBLK) break;
        const int cb = blk * 32;

        cp_wait0();
        __syncthreads();                 // staged A/B visible

        // prefetch biases for this thread's 4 clusters
        float2 bp[4];
        #pragma unroll
        for (int ni = 0; ni < 4; ni++) {
            int cl = cb + ((wc + ni * 8) >> 1) + tg;
            bp[ni] = g_b2p[cl < NCLUST ? cl : (NCLUST - 1)];
        }

        // --- MMA: 2 chains (aH*bH + aH*bL), 8 independent accs ---
        float acc[2][4][4];
        #pragma unroll
        for (int mi = 0; mi < 2; mi++)
            #pragma unroll
            for (int ni = 0; ni < 4; ni++)
                #pragma unroll
                for (int r = 0; r < 4; r++) acc[mi][ni][r] = 0.0f;

        #pragma unroll
        for (int ks = 0; ks < 8; ks++) {
            const uint32_t kb = ks * 32;
            uint32_t ah[2][4], bh[4][2], bl[4][2];
            #pragma unroll
            for (int mi = 0; mi < 2; mi++)
                ldsm_x4(ah[mi][0], ah[mi][1], ah[mi][2], ah[mi][3], aAddrH[mi] + kb);
            #pragma unroll
            for (int np = 0; np < 2; np++) {
                ldsm_x4(bh[2*np][0], bh[2*np][1], bh[2*np+1][0], bh[2*np+1][1],
                        bAddrH[np] + kb);
                ldsm_x4(bl[2*np][0], bl[2*np][1], bl[2*np+1][0], bl[2*np+1][1],
                        bAddrL[np] + kb);
            }
            #pragma unroll
            for (int mi = 0; mi < 2; mi++)
                #pragma unroll
                for (int ni = 0; ni < 4; ni++)
                    mma16816(acc[mi][ni], ah[mi], bh[ni]);
            #pragma unroll
            for (int mi = 0; mi < 2; mi++)
                #pragma unroll
                for (int ni = 0; ni < 4; ni++)
                    mma16816(acc[mi][ni], ah[mi], bl[ni]);
        }
        __syncthreads();                 // B consumed -> Cbuf may overwrite

        // --- epilogue: 2 row-passes, staged + dense __stcs stores (R12) ---
        const int vcl = (cb + 32 <= NCLUST) ? 32 : (NCLUST - cb);

        #pragma unroll
        for (int pass = 0; pass < 2; pass++) {
            #pragma unroll
            for (int ni = 0; ni < 4; ni++) {
                const int cl_loc = ((wc + ni * 8) >> 1) + tg;
                if (cb + cl_loc < NCLUST) {
                    float e1 = fexp(acc[pass][ni][0] + bp[ni].x);
                    float e2 = fexp(acc[pass][ni][1] + bp[ni].y);
                    float inv = frcp(1.0f + e1 + e2);
                    float* d = Cbuf + lrow0 * LDCB + 3 * cl_loc;
                    d[0] = inv; d[1] = e1 * inv; d[2] = e2 * inv;
                    e1 = fexp(acc[pass][ni][2] + bp[ni].x);
                    e2 = fexp(acc[pass][ni][3] + bp[ni].y);
                    inv = frcp(1.0f + e1 + e2);
                    d = Cbuf + (lrow0 + 8) * LDCB + 3 * cl_loc;
                    d[0] = inv; d[1] = e1 * inv; d[2] = e2 * inv;
                }
            }
            __syncthreads();

            if (vcl == 32) {
                #pragma unroll
                for (int i = tid; i < 64 * 24; i += 256) {
                    const int lr = i / 24, q = i - lr * 24;
                    const int grow = rbase + ((lr >> 4) << 5) + (pass << 4) + (lr & 15);
                    float4 val = *(float4*)(Cbuf + lr * LDCB + q * 4);
                    __stcs((float4*)(out + (size_t)grow * NOUT + 3 * cb + q * 4), val);
                }
            } else {
                for (int i = tid; i < 64 * 12; i += 256) {
                    const int lr = i / 12, q = i - lr * 12;
                    const int grow = rbase + ((lr >> 4) << 5) + (pass << 4) + (lr & 15);
                    float4 val = *(float4*)(Cbuf + lr * LDCB + q * 4);
                    __stcs((float4*)(out + (size_t)grow * NOUT + 3 * cb + q * 4), val);
                }
            }
            __syncthreads();
        }

        // --- stage next B via cp.async (Cbuf/B region free) ---
        const int nblk = (bi + 1) * CTAX + blockIdx.x;
        if (nblk < NBLK) {
            const int cc0 = nblk * 64;
            const uint4* bH = (const uint4*)(g_Bh + (size_t)(cc0 + sb_row) * NHID);
            const uint4* bL = (const uint4*)(g_Bl + (size_t)(cc0 + sb_row) * NHID);
            #pragma unroll
            for (int q = 0; q < 4; q++) {
                cp16(bStsH + q * 16, bH + sb_q + q);
                cp16(bStsL + q * 16, bL + sb_q + q);
            }
            cp_commit();
        }
    }
}

// ---------------------------------------------------------------------------
extern "C" void kernel_launch(void* const* d_in, const int* in_sizes, int n_in,
                              void* d_out, int out_size) {
    const float* z     = (const float*)d_in[0];
    const float* W1    = (const float*)d_in[1];
    const float* b1    = (const float*)d_in[2];
    const float* gamma = (const float*)d_in[3];
    const float* beta  = (const float*)d_in[4];
    const float* W2    = (const float*)d_in[5];
    const float* b2    = (const float*)d_in[6];
    float* out = (float*)d_out;

    k_init<<<1, 128>>>();
    k_h<<<BATCH / 128, 256>>>(z, W1, b1);
    k_bn<<<1, 128>>>(gamma, beta);
    k_split<<<SPLIT_HBLK + NCC_PAD * NHID / 256, 256>>>(W2, b2);

    cudaFuncSetAttribute(k_gemm, cudaFuncAttributeMaxDynamicSharedMemorySize,
                         SMEM_DYN);
    dim3 grid(CTAX, BATCH / 128);   // (41, 32) = 1312 CTAs ~ 3 waves @ occ 3
    k_gemm<<<grid, 256, SMEM_DYN>>>(out);
}

// round 17
// speedup vs baseline: 1.8782x; 1.2596x over previous
#include <cuda_runtime.h>
#include <cuda_fp16.h>
#include <math.h>
#include <cstdint>

#define BATCH  4096
#define NIN    32
#define NHID   128
#define NOUT   30000
#define NCLUST 10000
#define BN_EPS 1e-3f

#define NCC      20000
#define NCC_PAD  20480
#define NBLK     313
#define CTAX     41            // 1312 CTAs = 2.95 waves @ occ 3

// ---- scratch ----
__device__ float g_h[BATCH * NHID];
__device__ float g_sum[NHID];
__device__ float g_sumsq[NHID];
__device__ float g_scale[NHID];
__device__ float g_shift[NHID];
__device__ __half g_Ah[BATCH * NHID];          // fp16 activations
__device__ __half g_Bh[NCC_PAD * NHID];        // fp16 weights (single precision chain)
__device__ float2 g_b2p[10240];

// ---- MUFU-free exp / rcp ----------------------------------------------------
__device__ __forceinline__ float fexp(float x) {
    float t  = x * 1.4426950408889634f;
    float rf = t + 12582912.0f;
    int   ri = __float_as_int(rf) - 0x4B400000;
    float f  = t - (rf - 12582912.0f);
    float p = 1.3333558e-3f;
    p = fmaf(p, f, 9.6181291e-3f);
    p = fmaf(p, f, 5.5504109e-2f);
    p = fmaf(p, f, 2.4022651e-1f);
    p = fmaf(p, f, 6.9314718e-1f);
    p = fmaf(p, f, 1.0f);
    return __int_as_float(__float_as_int(p) + (ri << 23));
}
__device__ __forceinline__ float frcp(float d) {
    float r = __int_as_float(0x7EF127EAu - __float_as_int(d));
    #pragma unroll
    for (int i = 0; i < 2; i++) {
        float e = fmaf(-d, r, 1.0f);
        r = fmaf(r, e, r);
    }
    return r;
}

__device__ __forceinline__ uint32_t smem_u32(const void* p) {
    uint32_t a;
    asm("{ .reg .u64 t; cvta.to.shared.u64 t, %1; cvt.u32.u64 %0, t; }"
        : "=r"(a) : "l"(p));
    return a;
}
__device__ __forceinline__ void cp16(uint32_t dst, const void* src) {
    asm volatile("cp.async.cg.shared.global [%0], [%1], 16;"
                 :: "r"(dst), "l"(src));
}
__device__ __forceinline__ void cp_commit() {
    asm volatile("cp.async.commit_group;");
}
__device__ __forceinline__ void cp_wait0() {
    asm volatile("cp.async.wait_group 0;");
}
__device__ __forceinline__ void ldsm_x4(uint32_t& r0, uint32_t& r1,
                                        uint32_t& r2, uint32_t& r3, uint32_t a) {
    asm volatile("ldmatrix.sync.aligned.m8n8.x4.shared.b16 {%0,%1,%2,%3}, [%4];"
                 : "=r"(r0), "=r"(r1), "=r"(r2), "=r"(r3) : "r"(a));
}
__device__ __forceinline__ void mma16816(float* c, const uint32_t* a,
                                         const uint32_t* b) {
    asm volatile("mma.sync.aligned.m16n8k16.row.col.f32.f16.f16.f32 "
                 "{%0,%1,%2,%3}, {%4,%5,%6,%7}, {%8,%9}, {%0,%1,%2,%3};"
                 : "+f"(c[0]), "+f"(c[1]), "+f"(c[2]), "+f"(c[3])
                 : "r"(a[0]), "r"(a[1]), "r"(a[2]), "r"(a[3]),
                   "r"(b[0]), "r"(b[1]));
}

// ---------------------------------------------------------------------------
__global__ void k_init() {
    int i = threadIdx.x;
    if (i < NHID) { g_sum[i] = 0.0f; g_sumsq[i] = 0.0f; }
}

__global__ void k_h(const float* __restrict__ z,
                    const float* __restrict__ W1,
                    const float* __restrict__ b1) {
    __shared__ float zs[128][33];
    __shared__ float ws[128][33];
    __shared__ float ps[2][128];
    __shared__ float psq[2][128];

    const int tid   = threadIdx.x;
    const int rbase = blockIdx.x * 128;

    for (int idx = tid; idx < 128 * NIN; idx += 256) {
        int r = idx >> 5, k = idx & 31;
        zs[r][k] = z[(rbase + r) * NIN + k];
        ws[r][k] = W1[idx];
    }
    __syncthreads();

    const int col = tid & 127;
    const int rh  = tid >> 7;
    const float bb = b1[col];
    float ls = 0.0f, lsq = 0.0f;

    for (int r = rh * 64; r < rh * 64 + 64; r++) {
        float acc = bb;
        #pragma unroll
        for (int k = 0; k < NIN; k++)
            acc = fmaf(zs[r][k], ws[col][k], acc);
        g_h[(rbase + r) * NHID + col] = acc;
        ls += acc;
        lsq = fmaf(acc, acc, lsq);
    }
    ps[rh][col]  = ls;
    psq[rh][col] = lsq;
    __syncthreads();
    if (tid < 128) {
        atomicAdd(&g_sum[tid],   ps[0][tid]  + ps[1][tid]);
        atomicAdd(&g_sumsq[tid], psq[0][tid] + psq[1][tid]);
    }
}

__global__ void k_bn(const float* __restrict__ gamma,
                     const float* __restrict__ beta) {
    int c = threadIdx.x;
    if (c >= NHID) return;
    const float inv_b = 1.0f / (float)BATCH;
    float mu   = g_sum[c] * inv_b;
    float var  = g_sumsq[c] * inv_b - mu * mu;
    float rstd = rsqrtf(var + BN_EPS);
    float sc   = gamma[c] * rstd;
    g_scale[c] = sc;
    g_shift[c] = beta[c] - mu * sc;
}

// merged split kernel: blocks [0,2048) -> A fp16; rest -> W2 fp16 + b2p
#define SPLIT_HBLK 2048
__global__ void k_split(const float* __restrict__ W2,
                        const float* __restrict__ b2) {
    const int b = blockIdx.x;
    if (b < SPLIT_HBLK) {
        const int idx = b * 256 + threadIdx.x;
        const int k = idx & 127;
        float v = fmaxf(fmaf(g_h[idx], g_scale[k], g_shift[k]), 0.0f);
        g_Ah[idx] = __float2half_rn(v);
    } else {
        const int idx = (b - SPLIT_HBLK) * 256 + threadIdx.x;
        if (idx < 10240) {
            float2 bp = make_float2(0.0f, 0.0f);
            if (idx < NCLUST)
                bp = make_float2(b2[3 * idx + 1], b2[3 * idx + 2]);
            g_b2p[idx] = bp;
        }
        const int cc = idx >> 7;
        const int k  = idx & 127;
        float w = 0.0f;
        if (cc < NCC) {
            const int c = cc >> 1, j = cc & 1;
            w = W2[(size_t)(3 * c + 1 + j) * NHID + k];
        }
        g_Bh[idx] = __float2half_rn(w);
    }
}

// ---------------------------------------------------------------------------
// k_gemm: single-chain fp16 mma.sync GEMM (A, B both fp16-rn); occupancy 3.
// Dense two-pass staged copy-out (R12) unchanged.
// ---------------------------------------------------------------------------
#define LDA  136
#define LDCB 100

#define OFF_AH 0               // 34816 B
#define OFF_B  34816           // 17408 B (Cbuf 25600 overlays B + 8K)
#define SMEM_DYN 60416

extern "C" __global__ void __launch_bounds__(256, 3)
k_gemm(float* __restrict__ out) {
    extern __shared__ char sm[];
    float* Cbuf = (float*)(sm + OFF_B);

    const int tid   = threadIdx.x;
    const int wid   = tid >> 5;
    const int lid   = tid & 31;
    const int rbase = blockIdx.y * 128;

    const uint32_t smB = smem_u32(sm);

    // B-staging slot: 64 rows x 16 quads, 4 quads/thread
    const int sb_row = tid >> 2;
    const int sb_q   = (tid & 3) * 4;
    const uint32_t bSts = smB + OFF_B + (sb_row * LDA + sb_q * 8) * 2;

    // --- prologue: cp.async stage A + B(blk 0) ---
    {
        const int sa_row = tid >> 1;
        const int sa_q   = (tid & 1) * 8;
        const char* aH = (const char*)(g_Ah + (size_t)(rbase + sa_row) * NHID);
        #pragma unroll
        for (int q = 0; q < 8; q++) {
            const int qq = sa_q + q;
            cp16(smB + OFF_AH + (sa_row * LDA + qq * 8) * 2, aH + qq * 16);
        }
        const int cc0 = blockIdx.x * 64;
        const uint4* bH = (const uint4*)(g_Bh + (size_t)(cc0 + sb_row) * NHID);
        #pragma unroll
        for (int q = 0; q < 4; q++)
            cp16(bSts + q * 16, bH + sb_q + q);
        cp_commit();
    }

    const int wr = (wid >> 1) * 32;
    const int wc = (wid & 1)  * 32;

    const int g8 = lid & 7, q4 = lid >> 3;
    const int a_row  = g8 + ((q4 & 1) << 3);
    const int a_koff = (q4 >> 1) << 3;
    const int b_row  = g8 + ((q4 >> 1) << 3);
    const int b_koff = (q4 & 1) << 3;

    uint32_t aAddrH[2];
    #pragma unroll
    for (int mi = 0; mi < 2; mi++)
        aAddrH[mi] = smB + OFF_AH + ((wr + mi * 16 + a_row) * LDA + a_koff) * 2;
    uint32_t bAddr[2];
    #pragma unroll
    for (int np = 0; np < 2; np++)
        bAddr[np] = smB + OFF_B + ((wc + np * 16 + b_row) * LDA + b_koff) * 2;

    const int g = lid >> 2, tg = lid & 3;
    const int lrow0 = (wr >> 1) + g;

    const int nbi = (NBLK + CTAX - 1) / CTAX;   // 8

    for (int bi = 0; bi < nbi; bi++) {
        const int blk = bi * CTAX + blockIdx.x;
        if (blk >= NBLK) break;
        const int cb = blk * 32;

        cp_wait0();
        __syncthreads();                 // staged A/B visible

        // prefetch biases for this thread's 4 clusters
        float2 bp[4];
        #pragma unroll
        for (int ni = 0; ni < 4; ni++) {
            int cl = cb + ((wc + ni * 8) >> 1) + tg;
            bp[ni] = g_b2p[cl < NCLUST ? cl : (NCLUST - 1)];
        }

        // --- MMA: single chain, 8 independent accumulators ---
        float acc[2][4][4];
        #pragma unroll
        for (int mi = 0; mi < 2; mi++)
            #pragma unroll
            for (int ni = 0; ni < 4; ni++)
                #pragma unroll
                for (int r = 0; r < 4; r++) acc[mi][ni][r] = 0.0f;

        #pragma unroll
        for (int ks = 0; ks < 8; ks++) {
            const uint32_t kb = ks * 32;
            uint32_t ah[2][4], bh[4][2];
            #pragma unroll
            for (int mi = 0; mi < 2; mi++)
                ldsm_x4(ah[mi][0], ah[mi][1], ah[mi][2], ah[mi][3], aAddrH[mi] + kb);
            #pragma unroll
            for (int np = 0; np < 2; np++)
                ldsm_x4(bh[2*np][0], bh[2*np][1], bh[2*np+1][0], bh[2*np+1][1],
                        bAddr[np] + kb);
            #pragma unroll
            for (int mi = 0; mi < 2; mi++)
                #pragma unroll
                for (int ni = 0; ni < 4; ni++)
                    mma16816(acc[mi][ni], ah[mi], bh[ni]);
        }
        __syncthreads();                 // B consumed -> Cbuf may overwrite

        // --- epilogue: 2 row-passes, staged + dense __stcs stores ---
        const int vcl = (cb + 32 <= NCLUST) ? 32 : (NCLUST - cb);

        #pragma unroll
        for (int pass = 0; pass < 2; pass++) {
            #pragma unroll
            for (int ni = 0; ni < 4; ni++) {
                const int cl_loc = ((wc + ni * 8) >> 1) + tg;
                if (cb + cl_loc < NCLUST) {
                    float e1 = fexp(acc[pass][ni][0] + bp[ni].x);
                    float e2 = fexp(acc[pass][ni][1] + bp[ni].y);
                    float inv = frcp(1.0f + e1 + e2);
                    float* d = Cbuf + lrow0 * LDCB + 3 * cl_loc;
                    d[0] = inv; d[1] = e1 * inv; d[2] = e2 * inv;
                    e1 = fexp(acc[pass][ni][2] + bp[ni].x);
                    e2 = fexp(acc[pass][ni][3] + bp[ni].y);
                    inv = frcp(1.0f + e1 + e2);
                    d = Cbuf + (lrow0 + 8) * LDCB + 3 * cl_loc;
                    d[0] = inv; d[1] = e1 * inv; d[2] = e2 * inv;
                }
            }
            __syncthreads();

            if (vcl == 32) {
                #pragma unroll
                for (int i = tid; i < 64 * 24; i += 256) {
                    const int lr = i / 24, q = i - lr * 24;
                    const int grow = rbase + ((lr >> 4) << 5) + (pass << 4) + (lr & 15);
                    float4 val = *(float4*)(Cbuf + lr * LDCB + q * 4);
                    __stcs((float4*)(out + (size_t)grow * NOUT + 3 * cb + q * 4), val);
                }
            } else {
                for (int i = tid; i < 64 * 12; i += 256) {
                    const int lr = i / 12, q = i - lr * 12;
                    const int grow = rbase + ((lr >> 4) << 5) + (pass << 4) + (lr & 15);
                    float4 val = *(float4*)(Cbuf + lr * LDCB + q * 4);
                    __stcs((float4*)(out + (size_t)grow * NOUT + 3 * cb + q * 4), val);
                }
            }
            __syncthreads();
        }

        // --- stage next B via cp.async (Cbuf/B region free) ---
        const int nblk = (bi + 1) * CTAX + blockIdx.x;
        if (nblk < NBLK) {
            const int cc0 = nblk * 64;
            const uint4* bH = (const uint4*)(g_Bh + (size_t)(cc0 + sb_row) * NHID);
            #pragma unroll
            for (int q = 0; q < 4; q++)
                cp16(bSts + q * 16, bH + sb_q + q);
            cp_commit();
        }
    }
}

// ---------------------------------------------------------------------------
extern "C" void kernel_launch(void* const* d_in, const int* in_sizes, int n_in,
                              void* d_out, int out_size) {
    const float* z     = (const float*)d_in[0];
    const float* W1    = (const float*)d_in[1];
    const float* b1    = (const float*)d_in[2];
    const float* gamma = (const float*)d_in[3];
    const float* beta  = (const float*)d_in[4];
    const float* W2    = (const float*)d_in[5];
    const float* b2    = (const float*)d_in[6];
    float* out = (float*)d_out;

    k_init<<<1, 128>>>();
    k_h<<<BATCH / 128, 256>>>(z, W1, b1);
    k_bn<<<1, 128>>>(gamma, beta);
    k_split<<<SPLIT_HBLK + NCC_PAD * NHID / 256, 256>>>(W2, b2);

    cudaFuncSetAttribute(k_gemm, cudaFuncAttributeMaxDynamicSharedMemorySize,
                         SMEM_DYN);
    dim3 grid(CTAX, BATCH / 128);   // (41, 32) = 1312 CTAs ~ 3 waves @ occ 3
    k_gemm<<<grid, 256, SMEM_DYN>>>(out);
}